// round 1
// baseline (speedup 1.0000x reference)
#include <cuda_runtime.h>
#include <cuda_bf16.h>
#include <math_constants.h>

// Problem constants
#define BATCH 4
#define SEQ   2048
#define EMB   256
#define HEADS 8
#define HDIM  32
#define FFN   1024
#define NTOK  (BATCH * SEQ)   // 8192

// ---------------- scratch (no allocations allowed) ----------------
static __device__ float g_x   [NTOK * EMB];   // ln1 out
static __device__ float g_qkv [NTOK * 3 * EMB];
static __device__ float g_att [NTOK * EMB];   // attention out (pre out-proj)
static __device__ float g_src2[NTOK * EMB];   // src + attn@w_out^T
static __device__ float g_y   [NTOK * EMB];   // ln2 out
static __device__ float g_h   [NTOK * FFN];   // relu(y@w1^T+b1)

// ---------------- LayerNorm: one warp per token ----------------
__global__ void ln_kernel(const float* __restrict__ in,
                          const float* __restrict__ gamma,
                          const float* __restrict__ beta,
                          float* __restrict__ out) {
    int warp = threadIdx.x >> 5;
    int lane = threadIdx.x & 31;
    int token = blockIdx.x * 8 + warp;
    const float4* row = (const float4*)(in + (size_t)token * EMB);
    float4 v0 = row[lane];
    float4 v1 = row[lane + 32];
    float sum = (v0.x + v0.y) + (v0.z + v0.w) + (v1.x + v1.y) + (v1.z + v1.w);
    float sq  = v0.x*v0.x + v0.y*v0.y + v0.z*v0.z + v0.w*v0.w
              + v1.x*v1.x + v1.y*v1.y + v1.z*v1.z + v1.w*v1.w;
    #pragma unroll
    for (int off = 16; off > 0; off >>= 1) {
        sum += __shfl_xor_sync(0xffffffffu, sum, off);
        sq  += __shfl_xor_sync(0xffffffffu, sq,  off);
    }
    float mu  = sum * (1.0f / EMB);
    float var = sq * (1.0f / EMB) - mu * mu;
    float rs  = rsqrtf(var + 1e-5f);

    const float4* g4 = (const float4*)gamma;
    const float4* b4 = (const float4*)beta;
    float4 ga = g4[lane], gb = g4[lane + 32];
    float4 ba = b4[lane], bb = b4[lane + 32];
    float4 o0, o1;
    o0.x = (v0.x - mu) * rs * ga.x + ba.x;
    o0.y = (v0.y - mu) * rs * ga.y + ba.y;
    o0.z = (v0.z - mu) * rs * ga.z + ba.z;
    o0.w = (v0.w - mu) * rs * ga.w + ba.w;
    o1.x = (v1.x - mu) * rs * gb.x + bb.x;
    o1.y = (v1.y - mu) * rs * gb.y + bb.y;
    o1.z = (v1.z - mu) * rs * gb.z + bb.z;
    o1.w = (v1.w - mu) * rs * gb.w + bb.w;
    float4* orow = (float4*)(out + (size_t)token * EMB);
    orow[lane]      = o0;
    orow[lane + 32] = o1;
}

// ---------------- NT GEMM: C[M,N] = A[M,K] * W[N,K]^T (+bias)(+relu)(+resid) ----------------
// 64x64 tile, BK=16, 256 threads, 4x4 per thread.
template<bool HAS_BIAS, bool RELU, bool RESID>
__global__ void __launch_bounds__(256)
gemm_nt_kernel(const float* __restrict__ A, const float* __restrict__ W,
               const float* __restrict__ bias, const float* __restrict__ resid,
               float* __restrict__ C, int M, int N, int K) {
    __shared__ float As[16][64];
    __shared__ float Ws[16][64];
    int tid = threadIdx.x;
    int tx = tid & 15;        // 0..15 -> N
    int ty = tid >> 4;        // 0..15 -> M
    int m0 = blockIdx.y * 64;
    int n0 = blockIdx.x * 64;
    int lr = tid >> 2;         // 0..63 : tile row for loading
    int lc = (tid & 3) * 4;    // 0,4,8,12 : k-offset for loading

    float acc[4][4];
    #pragma unroll
    for (int i = 0; i < 4; i++)
        #pragma unroll
        for (int j = 0; j < 4; j++) acc[i][j] = 0.0f;

    for (int k0 = 0; k0 < K; k0 += 16) {
        float4 a = *(const float4*)&A[(size_t)(m0 + lr) * K + k0 + lc];
        float4 w = *(const float4*)&W[(size_t)(n0 + lr) * K + k0 + lc];
        As[lc + 0][lr] = a.x; As[lc + 1][lr] = a.y; As[lc + 2][lr] = a.z; As[lc + 3][lr] = a.w;
        Ws[lc + 0][lr] = w.x; Ws[lc + 1][lr] = w.y; Ws[lc + 2][lr] = w.z; Ws[lc + 3][lr] = w.w;
        __syncthreads();
        #pragma unroll
        for (int k = 0; k < 16; k++) {
            float4 av = *(const float4*)&As[k][ty * 4];
            float4 wv = *(const float4*)&Ws[k][tx * 4];
            float ar[4] = {av.x, av.y, av.z, av.w};
            float wr[4] = {wv.x, wv.y, wv.z, wv.w};
            #pragma unroll
            for (int i = 0; i < 4; i++)
                #pragma unroll
                for (int j = 0; j < 4; j++)
                    acc[i][j] += ar[i] * wr[j];
        }
        __syncthreads();
    }

    int col = n0 + tx * 4;
    float4 bb = make_float4(0.f, 0.f, 0.f, 0.f);
    if (HAS_BIAS) bb = *(const float4*)&bias[col];
    #pragma unroll
    for (int i = 0; i < 4; i++) {
        int row = m0 + ty * 4 + i;
        float4 v = make_float4(acc[i][0], acc[i][1], acc[i][2], acc[i][3]);
        if (HAS_BIAS) { v.x += bb.x; v.y += bb.y; v.z += bb.z; v.w += bb.w; }
        if (RELU) {
            v.x = fmaxf(v.x, 0.f); v.y = fmaxf(v.y, 0.f);
            v.z = fmaxf(v.z, 0.f); v.w = fmaxf(v.w, 0.f);
        }
        if (RESID) {
            float4 r = *(const float4*)&resid[(size_t)row * N + col];
            v.x += r.x; v.y += r.y; v.z += r.z; v.w += r.w;
        }
        *(float4*)&C[(size_t)row * N + col] = v;
    }
}

// ---------------- Attention: flash-style, thread-per-query ----------------
// grid: (SEQ/128, BATCH*HEADS), block: 128 threads
__global__ void __launch_bounds__(128)
attn_kernel(const float* __restrict__ qkv, float* __restrict__ att) {
    __shared__ float4 Ks[128 * 8];
    __shared__ float4 Vs[128 * 8];
    int tid = threadIdx.x;
    int bh  = blockIdx.y;
    int b   = bh >> 3;
    int h   = bh & 7;
    int q   = blockIdx.x * 128 + tid;

    const float scale = 0.17677669529663687f;  // 1/sqrt(32)
    const float4* qrow = (const float4*)(qkv + (size_t)(b * SEQ + q) * (3 * EMB) + h * HDIM);
    float4 q4[8];
    #pragma unroll
    for (int j = 0; j < 8; j++) {
        q4[j] = qrow[j];
        q4[j].x *= scale; q4[j].y *= scale; q4[j].z *= scale; q4[j].w *= scale;
    }

    float4 acc4[8];
    #pragma unroll
    for (int j = 0; j < 8; j++) acc4[j] = make_float4(0.f, 0.f, 0.f, 0.f);
    float m = -1e30f;
    float l = 0.f;

    for (int k0 = 0; k0 < SEQ; k0 += 128) {
        __syncthreads();
        const float4* kbase = (const float4*)(qkv + (size_t)(b * SEQ + k0) * (3 * EMB) + EMB     + h * HDIM);
        const float4* vbase = (const float4*)(qkv + (size_t)(b * SEQ + k0) * (3 * EMB) + 2 * EMB + h * HDIM);
        #pragma unroll
        for (int i = 0; i < 8; i++) {
            int idx = tid + i * 128;      // 0..1023
            int r = idx >> 3, c = idx & 7;
            Ks[idx] = kbase[(size_t)r * 192 + c];   // 192 = 768/4 float4 row stride
            Vs[idx] = vbase[(size_t)r * 192 + c];
        }
        __syncthreads();

        #pragma unroll 4
        for (int kk = 0; kk < 128; kk++) {
            const float4* kr = &Ks[kk * 8];
            float s0 = 0.f, s1 = 0.f, s2 = 0.f, s3 = 0.f;
            #pragma unroll
            for (int j = 0; j < 8; j++) {
                float4 kv = kr[j];
                s0 += q4[j].x * kv.x;
                s1 += q4[j].y * kv.y;
                s2 += q4[j].z * kv.z;
                s3 += q4[j].w * kv.w;
            }
            float s = (s0 + s1) + (s2 + s3);
            if (s > m) {
                float corr = __expf(m - s);
                m = s;
                l *= corr;
                #pragma unroll
                for (int j = 0; j < 8; j++) {
                    acc4[j].x *= corr; acc4[j].y *= corr;
                    acc4[j].z *= corr; acc4[j].w *= corr;
                }
            }
            float p = __expf(s - m);
            l += p;
            const float4* vr = &Vs[kk * 8];
            #pragma unroll
            for (int j = 0; j < 8; j++) {
                float4 vv = vr[j];
                acc4[j].x += p * vv.x; acc4[j].y += p * vv.y;
                acc4[j].z += p * vv.z; acc4[j].w += p * vv.w;
            }
        }
    }

    float inv = 1.0f / l;
    float4* orow = (float4*)(att + (size_t)(b * SEQ + q) * EMB + h * HDIM);
    #pragma unroll
    for (int j = 0; j < 8; j++) {
        float4 v = acc4[j];
        v.x *= inv; v.y *= inv; v.z *= inv; v.w *= inv;
        orow[j] = v;
    }
}

// ---------------- launcher ----------------
extern "C" void kernel_launch(void* const* d_in, const int* in_sizes, int n_in,
                              void* d_out, int out_size) {
    const float* src   = (const float*)d_in[0];
    const float* w_in  = (const float*)d_in[1];
    const float* w_out = (const float*)d_in[2];
    const float* w1    = (const float*)d_in[3];
    const float* b1    = (const float*)d_in[4];
    const float* w2    = (const float*)d_in[5];
    const float* b2    = (const float*)d_in[6];
    const float* g1    = (const float*)d_in[7];
    const float* be1   = (const float*)d_in[8];
    const float* g2    = (const float*)d_in[9];
    const float* be2   = (const float*)d_in[10];
    float* out = (float*)d_out;

    float *x, *qkv, *att, *src2, *y, *h;
    cudaGetSymbolAddress((void**)&x,    g_x);
    cudaGetSymbolAddress((void**)&qkv,  g_qkv);
    cudaGetSymbolAddress((void**)&att,  g_att);
    cudaGetSymbolAddress((void**)&src2, g_src2);
    cudaGetSymbolAddress((void**)&y,    g_y);
    cudaGetSymbolAddress((void**)&h,    g_h);

    // 1) x = LN(src)
    ln_kernel<<<NTOK / 8, 256>>>(src, g1, be1, x);
    // 2) qkv = x @ w_in^T          [8192, 768]
    gemm_nt_kernel<false, false, false><<<dim3(768 / 64, NTOK / 64), 256>>>(
        x, w_in, nullptr, nullptr, qkv, NTOK, 768, EMB);
    // 3) att = softmax(q k^T / sqrt(d)) v
    attn_kernel<<<dim3(SEQ / 128, BATCH * HEADS), 128>>>(qkv, att);
    // 4) src2 = src + att @ w_out^T
    gemm_nt_kernel<false, false, true><<<dim3(EMB / 64, NTOK / 64), 256>>>(
        att, w_out, nullptr, src, src2, NTOK, EMB, EMB);
    // 5) y = LN(src2)
    ln_kernel<<<NTOK / 8, 256>>>(src2, g2, be2, y);
    // 6) h = relu(y @ w1^T + b1)   [8192, 1024]
    gemm_nt_kernel<true, true, false><<<dim3(FFN / 64, NTOK / 64), 256>>>(
        y, w1, b1, nullptr, h, NTOK, FFN, EMB);
    // 7) out = src2 + h @ w2^T + b2
    gemm_nt_kernel<true, false, true><<<dim3(EMB / 64, NTOK / 64), 256>>>(
        h, w2, b2, src2, out, NTOK, EMB, FFN);
}

// round 3
// speedup vs baseline: 1.3664x; 1.3664x over previous
#include <cuda_runtime.h>
#include <cuda_bf16.h>
#include <cstdint>

// Problem constants
#define BATCH 4
#define SEQ   2048
#define EMB   256
#define HEADS 8
#define HDIM  32
#define FFN   1024
#define NTOK  (BATCH * SEQ)   // 8192
#define K3E   (3 * EMB)       // 768 : split K for E-dim GEMMs
#define K3F   (3 * FFN)       // 3072: split K for FFN2

// ---------------- scratch (no allocations allowed) ----------------
static __device__ float g_qkv [NTOK * K3E];          // qkv fp32 [8192,768]
static __device__ float g_src2[NTOK * EMB];          // src + attn@w_out^T
static __device__ __nv_bfloat16 g_xs  [NTOK * K3E];  // split LN1 out   (A-style: hi,lo,hi)
static __device__ __nv_bfloat16 g_atts[NTOK * K3E];  // split attn out  (A-style)
static __device__ __nv_bfloat16 g_ys  [NTOK * K3E];  // split LN2 out   (A-style)
static __device__ __nv_bfloat16 g_hs  [NTOK * K3F];  // split relu(ffn1)(A-style)
static __device__ __nv_bfloat16 g_wsin [768  * K3E]; // split weights   (B-style: hi,hi,lo)
static __device__ __nv_bfloat16 g_wsout[256  * K3E];
static __device__ __nv_bfloat16 g_w1s  [1024 * K3E];
static __device__ __nv_bfloat16 g_w2s  [256  * K3F];

// ---------------- helpers ----------------
__device__ __forceinline__ uint32_t smem_u32(const void* p) {
    uint32_t a;
    asm("{ .reg .u64 t; cvta.to.shared.u64 t, %1; cvt.u32.u64 %0, t; }" : "=r"(a) : "l"(p));
    return a;
}
__device__ __forceinline__ void cp_async16(uint32_t saddr, const void* gaddr) {
    asm volatile("cp.async.cg.shared.global [%0], [%1], 16;" :: "r"(saddr), "l"(gaddr));
}
__device__ __forceinline__ void cp_commit() {
    asm volatile("cp.async.commit_group;");
}
template<int N>
__device__ __forceinline__ void cp_wait() {
    asm volatile("cp.async.wait_group %0;" :: "n"(N));
}
__device__ __forceinline__ void ldsm_x4(uint32_t* r, uint32_t addr) {
    asm volatile("ldmatrix.sync.aligned.m8n8.x4.shared.b16 {%0,%1,%2,%3}, [%4];"
                 : "=r"(r[0]), "=r"(r[1]), "=r"(r[2]), "=r"(r[3]) : "r"(addr));
}
__device__ __forceinline__ void mma16816(float* c, const uint32_t* a, uint32_t b0, uint32_t b1) {
    asm volatile("mma.sync.aligned.m16n8k16.row.col.f32.bf16.bf16.f32 "
                 "{%0,%1,%2,%3}, {%4,%5,%6,%7}, {%8,%9}, {%0,%1,%2,%3};"
                 : "+f"(c[0]), "+f"(c[1]), "+f"(c[2]), "+f"(c[3])
                 : "r"(a[0]), "r"(a[1]), "r"(a[2]), "r"(a[3]), "r"(b0), "r"(b1));
}
__device__ __forceinline__ float fast_exp2(float x) {
    float y; asm("ex2.approx.ftz.f32 %0, %1;" : "=f"(y) : "f"(x)); return y;
}
__device__ __forceinline__ void split1(float v, __nv_bfloat16& h, __nv_bfloat16& l) {
    h = __float2bfloat16(v);
    l = __float2bfloat16(v - __bfloat162float(h));
}
// write float4 as (hi,lo,hi) into a 3*256-wide bf16 row at column `col`
__device__ __forceinline__ void split_store4_256(__nv_bfloat16* rowbase, int col, float4 v) {
    __nv_bfloat16 hx, lx, hy, ly, hz, lz, hw, lw;
    split1(v.x, hx, lx); split1(v.y, hy, ly); split1(v.z, hz, lz); split1(v.w, hw, lw);
    *(__nv_bfloat162*)(rowbase + col)           = __halves2bfloat162(hx, hy);
    *(__nv_bfloat162*)(rowbase + col + 2)       = __halves2bfloat162(hz, hw);
    *(__nv_bfloat162*)(rowbase + 256 + col)     = __halves2bfloat162(lx, ly);
    *(__nv_bfloat162*)(rowbase + 256 + col + 2) = __halves2bfloat162(lz, lw);
    *(__nv_bfloat162*)(rowbase + 512 + col)     = __halves2bfloat162(hx, hy);
    *(__nv_bfloat162*)(rowbase + 512 + col + 2) = __halves2bfloat162(hz, hw);
}

// ---------------- LayerNorm -> split bf16 (A-style), one warp per token ----------------
__global__ void ln_split_kernel(const float* __restrict__ in,
                                const float* __restrict__ gamma,
                                const float* __restrict__ beta,
                                __nv_bfloat16* __restrict__ out3) {
    int warp = threadIdx.x >> 5;
    int lane = threadIdx.x & 31;
    int token = blockIdx.x * 8 + warp;
    const float4* row = (const float4*)(in + (size_t)token * EMB);
    float4 v0 = row[lane];
    float4 v1 = row[lane + 32];
    float sum = (v0.x + v0.y) + (v0.z + v0.w) + (v1.x + v1.y) + (v1.z + v1.w);
    float sq  = v0.x*v0.x + v0.y*v0.y + v0.z*v0.z + v0.w*v0.w
              + v1.x*v1.x + v1.y*v1.y + v1.z*v1.z + v1.w*v1.w;
    #pragma unroll
    for (int off = 16; off > 0; off >>= 1) {
        sum += __shfl_xor_sync(0xffffffffu, sum, off);
        sq  += __shfl_xor_sync(0xffffffffu, sq,  off);
    }
    float mu  = sum * (1.0f / EMB);
    float var = sq * (1.0f / EMB) - mu * mu;
    float rs  = rsqrtf(var + 1e-5f);

    const float4* g4 = (const float4*)gamma;
    const float4* b4 = (const float4*)beta;
    float4 ga = g4[lane], gb = g4[lane + 32];
    float4 ba = b4[lane], bb = b4[lane + 32];
    float4 o0, o1;
    o0.x = (v0.x - mu) * rs * ga.x + ba.x;
    o0.y = (v0.y - mu) * rs * ga.y + ba.y;
    o0.z = (v0.z - mu) * rs * ga.z + ba.z;
    o0.w = (v0.w - mu) * rs * ga.w + ba.w;
    o1.x = (v1.x - mu) * rs * gb.x + bb.x;
    o1.y = (v1.y - mu) * rs * gb.y + bb.y;
    o1.z = (v1.z - mu) * rs * gb.z + bb.z;
    o1.w = (v1.w - mu) * rs * gb.w + bb.w;
    __nv_bfloat16* rb = out3 + (size_t)token * K3E;
    split_store4_256(rb, lane * 4, o0);
    split_store4_256(rb, 128 + lane * 4, o1);
}

// ---------------- weight split: [N,K] fp32 -> [N,3K] bf16 (B-style: hi,hi,lo) ----------------
__global__ void split_w_kernel(const float* __restrict__ w, __nv_bfloat16* __restrict__ out,
                               int NK, int K) {
    int i = blockIdx.x * 256 + threadIdx.x;
    if (i >= NK) return;
    int r = i / K, c = i - r * K;
    float v = w[i];
    __nv_bfloat16 h, l;
    split1(v, h, l);
    size_t base = (size_t)r * 3 * K;
    out[base + c]         = h;
    out[base + K + c]     = h;
    out[base + 2 * K + c] = l;
}

// ---------------- mma.sync split-bf16 GEMM ----------------
// C[M,N] = A''[M,K3] * B''[N,K3]^T  (bf16 HMMA, fp32 accum)
// CTA tile 128x128, BK=64 bf16 (128B swizzled rows), 2-stage cp.async pipeline.
// 8 warps in 2x4: warp tile 64x32 (4 m16 x 4 n8).
// EPI: 0=plain fp32, 1=+resid fp32, 2=+bias,relu -> split bf16 (NS-wide), 3=+bias,+resid fp32
#define STAGE_BYTES 32768       // 16KB A + 16KB B
template<int EPI>
__global__ void __launch_bounds__(256)
gemm_mma_kernel(const __nv_bfloat16* __restrict__ A, const __nv_bfloat16* __restrict__ B,
                const float* __restrict__ bias, const float* __restrict__ resid,
                float* __restrict__ outF, __nv_bfloat16* __restrict__ outS,
                int K3, int N, int NS) {
    extern __shared__ char smem[];
    const int tid  = threadIdx.x;
    const int wid  = tid >> 5;
    const int lane = tid & 31;
    const int m0 = blockIdx.y * 128;
    const int n0 = blockIdx.x * 128;
    const int wm = (wid >> 2) * 64;   // warp M offset
    const int wn = (wid & 3) * 32;    // warp N offset
    const uint32_t sbase = smem_u32(smem);
    const size_t rbytes = (size_t)K3 * 2;

    float acc[4][4][4];
    #pragma unroll
    for (int i = 0; i < 4; i++)
        #pragma unroll
        for (int j = 0; j < 4; j++)
            #pragma unroll
            for (int r = 0; r < 4; r++) acc[i][j][r] = 0.f;

    const int lrow = tid >> 3;          // 0..31
    const int lcol = (tid & 7) * 16;    // byte within 128B row
    const char* gA0 = (const char*)A + (size_t)m0 * rbytes;
    const char* gB0 = (const char*)B + (size_t)n0 * rbytes;

    const int nchunk = K3 >> 6;

    // issue loads for chunk `c` into stage `s`
    auto issue = [&](int c, int s) {
        uint32_t sA = sbase + s * STAGE_BYTES;
        uint32_t sB = sA + 16384;
        const char* gA = gA0 + (size_t)c * 128;
        const char* gB = gB0 + (size_t)c * 128;
        #pragma unroll
        for (int i = 0; i < 4; i++) {
            int r = lrow + i * 32;
            int so = r * 128 + lcol;
            so ^= (so >> 3) & 0x70;
            cp_async16(sA + so, gA + (size_t)r * rbytes + lcol);
            cp_async16(sB + so, gB + (size_t)r * rbytes + lcol);
        }
        cp_commit();
    };

    issue(0, 0);
    for (int c = 0; c < nchunk; ++c) {
        int s = c & 1;
        if (c + 1 < nchunk) { issue(c + 1, s ^ 1); cp_wait<1>(); }
        else               { cp_wait<0>(); }
        __syncthreads();

        uint32_t sA = sbase + s * STAGE_BYTES;
        uint32_t sB = sA + 16384;
        #pragma unroll
        for (int k16 = 0; k16 < 4; ++k16) {
            // A fragments: 4 m16 tiles
            uint32_t af[4][4];
            #pragma unroll
            for (int mi = 0; mi < 4; ++mi) {
                int row = wm + mi * 16 + (lane & 15);
                int col = k16 * 32 + ((lane >> 4) << 4);
                int so = row * 128 + col;
                so ^= (so >> 3) & 0x70;
                ldsm_x4(af[mi], sA + so);
            }
            // B fragments: 2 x4 loads cover 4 n8 tiles
            uint32_t bf[2][4];
            #pragma unroll
            for (int nb = 0; nb < 2; ++nb) {
                int grp = lane >> 3;
                int row = wn + nb * 16 + ((grp >> 1) << 3) + (lane & 7);
                int col = k16 * 32 + ((grp & 1) << 4);
                int so = row * 128 + col;
                so ^= (so >> 3) & 0x70;
                ldsm_x4(bf[nb], sB + so);
            }
            #pragma unroll
            for (int mi = 0; mi < 4; ++mi)
                #pragma unroll
                for (int nj = 0; nj < 4; ++nj)
                    mma16816(acc[mi][nj], af[mi],
                             bf[nj >> 1][(nj & 1) * 2], bf[nj >> 1][(nj & 1) * 2 + 1]);
        }
        __syncthreads();
    }

    // ---------------- epilogue ----------------
    #pragma unroll
    for (int mi = 0; mi < 4; ++mi) {
        #pragma unroll
        for (int nj = 0; nj < 4; ++nj) {
            int row = m0 + wm + mi * 16 + (lane >> 2);
            int col = n0 + wn + nj * 8 + ((lane & 3) << 1);
            float v0 = acc[mi][nj][0], v1 = acc[mi][nj][1];
            float v2 = acc[mi][nj][2], v3 = acc[mi][nj][3];
            if (EPI == 0) {
                *(float2*)&outF[(size_t)row * N + col]       = make_float2(v0, v1);
                *(float2*)&outF[(size_t)(row + 8) * N + col] = make_float2(v2, v3);
            } else if (EPI == 1) {
                float2 r0 = *(const float2*)&resid[(size_t)row * N + col];
                float2 r1 = *(const float2*)&resid[(size_t)(row + 8) * N + col];
                *(float2*)&outF[(size_t)row * N + col]       = make_float2(v0 + r0.x, v1 + r0.y);
                *(float2*)&outF[(size_t)(row + 8) * N + col] = make_float2(v2 + r1.x, v3 + r1.y);
            } else if (EPI == 3) {
                float2 bv = *(const float2*)&bias[col];
                float2 r0 = *(const float2*)&resid[(size_t)row * N + col];
                float2 r1 = *(const float2*)&resid[(size_t)(row + 8) * N + col];
                *(float2*)&outF[(size_t)row * N + col]       = make_float2(v0 + bv.x + r0.x, v1 + bv.y + r0.y);
                *(float2*)&outF[(size_t)(row + 8) * N + col] = make_float2(v2 + bv.x + r1.x, v3 + bv.y + r1.y);
            } else { // EPI == 2: bias + relu -> split bf16 (hi,lo,hi), NS-wide segments
                float2 bv = *(const float2*)&bias[col];
                float a0 = fmaxf(v0 + bv.x, 0.f), a1 = fmaxf(v1 + bv.y, 0.f);
                float a2 = fmaxf(v2 + bv.x, 0.f), a3 = fmaxf(v3 + bv.y, 0.f);
                __nv_bfloat16 h0,l0,h1,l1,h2,l2,h3,l3;
                split1(a0,h0,l0); split1(a1,h1,l1); split1(a2,h2,l2); split1(a3,h3,l3);
                __nv_bfloat16* r0b = outS + (size_t)row * 3 * NS;
                __nv_bfloat16* r1b = outS + (size_t)(row + 8) * 3 * NS;
                *(__nv_bfloat162*)(r0b + col)          = __halves2bfloat162(h0, h1);
                *(__nv_bfloat162*)(r0b + NS + col)     = __halves2bfloat162(l0, l1);
                *(__nv_bfloat162*)(r0b + 2 * NS + col) = __halves2bfloat162(h0, h1);
                *(__nv_bfloat162*)(r1b + col)          = __halves2bfloat162(h2, h3);
                *(__nv_bfloat162*)(r1b + NS + col)     = __halves2bfloat162(l2, l3);
                *(__nv_bfloat162*)(r1b + 2 * NS + col) = __halves2bfloat162(h2, h3);
            }
        }
    }
}

// ---------------- Attention: flash-style, thread-per-query, split-bf16 output ----------------
__global__ void __launch_bounds__(128)
attn_kernel(const float* __restrict__ qkv, __nv_bfloat16* __restrict__ att3) {
    __shared__ float4 Ks[128 * 8];
    __shared__ float4 Vs[128 * 8];
    int tid = threadIdx.x;
    int bh  = blockIdx.y;
    int b   = bh >> 3;
    int h   = bh & 7;
    int q   = blockIdx.x * 128 + tid;

    // scale * log2(e): softmax in base-2
    const float scale2 = 0.17677669529663687f * 1.4426950408889634f;
    const float4* qrow = (const float4*)(qkv + (size_t)(b * SEQ + q) * K3E + h * HDIM);
    float4 q4[8];
    #pragma unroll
    for (int j = 0; j < 8; j++) {
        q4[j] = qrow[j];
        q4[j].x *= scale2; q4[j].y *= scale2; q4[j].z *= scale2; q4[j].w *= scale2;
    }

    float4 acc4[8];
    #pragma unroll
    for (int j = 0; j < 8; j++) acc4[j] = make_float4(0.f, 0.f, 0.f, 0.f);
    float m = -1e30f;
    float l = 0.f;

    for (int k0 = 0; k0 < SEQ; k0 += 128) {
        __syncthreads();
        const float4* kbase = (const float4*)(qkv + (size_t)(b * SEQ + k0) * K3E + EMB     + h * HDIM);
        const float4* vbase = (const float4*)(qkv + (size_t)(b * SEQ + k0) * K3E + 2 * EMB + h * HDIM);
        #pragma unroll
        for (int i = 0; i < 8; i++) {
            int idx = tid + i * 128;
            int r = idx >> 3, c = idx & 7;
            Ks[idx] = kbase[(size_t)r * 192 + c];   // 192 = 768/4 float4 row stride
            Vs[idx] = vbase[(size_t)r * 192 + c];
        }
        __syncthreads();

        #pragma unroll 4
        for (int kk = 0; kk < 128; kk++) {
            const float4* kr = &Ks[kk * 8];
            float s0 = 0.f, s1 = 0.f, s2 = 0.f, s3 = 0.f;
            #pragma unroll
            for (int j = 0; j < 8; j++) {
                float4 kv = kr[j];
                s0 += q4[j].x * kv.x;
                s1 += q4[j].y * kv.y;
                s2 += q4[j].z * kv.z;
                s3 += q4[j].w * kv.w;
            }
            float s = (s0 + s1) + (s2 + s3);
            if (s > m) {
                float corr = fast_exp2(m - s);
                m = s;
                l *= corr;
                #pragma unroll
                for (int j = 0; j < 8; j++) {
                    acc4[j].x *= corr; acc4[j].y *= corr;
                    acc4[j].z *= corr; acc4[j].w *= corr;
                }
            }
            float p = fast_exp2(s - m);
            l += p;
            const float4* vr = &Vs[kk * 8];
            #pragma unroll
            for (int j = 0; j < 8; j++) {
                float4 vv = vr[j];
                acc4[j].x += p * vv.x; acc4[j].y += p * vv.y;
                acc4[j].z += p * vv.z; acc4[j].w += p * vv.w;
            }
        }
    }

    float inv = 1.0f / l;
    __nv_bfloat16* rb = att3 + (size_t)(b * SEQ + q) * K3E;
    #pragma unroll
    for (int j = 0; j < 8; j++) {
        float4 v = acc4[j];
        v.x *= inv; v.y *= inv; v.z *= inv; v.w *= inv;
        split_store4_256(rb, h * HDIM + j * 4, v);
    }
}

// ---------------- launcher ----------------
extern "C" void kernel_launch(void* const* d_in, const int* in_sizes, int n_in,
                              void* d_out, int out_size) {
    const float* src   = (const float*)d_in[0];
    const float* w_in  = (const float*)d_in[1];
    const float* w_out = (const float*)d_in[2];
    const float* w1    = (const float*)d_in[3];
    const float* b1    = (const float*)d_in[4];
    const float* w2    = (const float*)d_in[5];
    const float* b2    = (const float*)d_in[6];
    const float* g1    = (const float*)d_in[7];
    const float* be1   = (const float*)d_in[8];
    const float* g2    = (const float*)d_in[9];
    const float* be2   = (const float*)d_in[10];
    float* out = (float*)d_out;

    float *qkv, *src2;
    __nv_bfloat16 *xs, *atts, *ys, *hs, *wsin, *wsout, *w1s, *w2s;
    cudaGetSymbolAddress((void**)&qkv,   g_qkv);
    cudaGetSymbolAddress((void**)&src2,  g_src2);
    cudaGetSymbolAddress((void**)&xs,    g_xs);
    cudaGetSymbolAddress((void**)&atts,  g_atts);
    cudaGetSymbolAddress((void**)&ys,    g_ys);
    cudaGetSymbolAddress((void**)&hs,    g_hs);
    cudaGetSymbolAddress((void**)&wsin,  g_wsin);
    cudaGetSymbolAddress((void**)&wsout, g_wsout);
    cudaGetSymbolAddress((void**)&w1s,   g_w1s);
    cudaGetSymbolAddress((void**)&w2s,   g_w2s);

    const int SMEM = 2 * STAGE_BYTES;   // 64KB
    cudaFuncSetAttribute(gemm_mma_kernel<0>, cudaFuncAttributeMaxDynamicSharedMemorySize, SMEM);
    cudaFuncSetAttribute(gemm_mma_kernel<1>, cudaFuncAttributeMaxDynamicSharedMemorySize, SMEM);
    cudaFuncSetAttribute(gemm_mma_kernel<2>, cudaFuncAttributeMaxDynamicSharedMemorySize, SMEM);
    cudaFuncSetAttribute(gemm_mma_kernel<3>, cudaFuncAttributeMaxDynamicSharedMemorySize, SMEM);

    // weight splits (B-style)
    split_w_kernel<<<(768 * 256 + 255) / 256, 256>>>(w_in,  wsin,  768 * 256, 256);
    split_w_kernel<<<(256 * 256 + 255) / 256, 256>>>(w_out, wsout, 256 * 256, 256);
    split_w_kernel<<<(1024 * 256 + 255) / 256, 256>>>(w1,   w1s,  1024 * 256, 256);
    split_w_kernel<<<(256 * 1024 + 255) / 256, 256>>>(w2,   w2s,  256 * 1024, 1024);

    // 1) xs = split(LN1(src))
    ln_split_kernel<<<NTOK / 8, 256>>>(src, g1, be1, xs);
    // 2) qkv = xs @ wsin^T   [8192,768] fp32
    gemm_mma_kernel<0><<<dim3(768 / 128, NTOK / 128), 256, SMEM>>>(
        xs, wsin, nullptr, nullptr, qkv, nullptr, K3E, 768, 0);
    // 3) atts = split(softmax(qk^T)v)
    attn_kernel<<<dim3(SEQ / 128, BATCH * HEADS), 128>>>(qkv, atts);
    // 4) src2 = src + atts @ wsout^T
    gemm_mma_kernel<1><<<dim3(256 / 128, NTOK / 128), 256, SMEM>>>(
        atts, wsout, nullptr, src, src2, nullptr, K3E, 256, 0);
    // 5) ys = split(LN2(src2))
    ln_split_kernel<<<NTOK / 8, 256>>>(src2, g2, be2, ys);
    // 6) hs = split(relu(ys @ w1s^T + b1))
    gemm_mma_kernel<2><<<dim3(1024 / 128, NTOK / 128), 256, SMEM>>>(
        ys, w1s, b1, nullptr, nullptr, hs, K3E, 1024, FFN);
    // 7) out = src2 + hs @ w2s^T + b2
    gemm_mma_kernel<3><<<dim3(256 / 128, NTOK / 128), 256, SMEM>>>(
        hs, w2s, b2, src2, out, nullptr, K3F, 256, 0);
}

// round 4
// speedup vs baseline: 3.8026x; 2.7830x over previous
#include <cuda_runtime.h>
#include <cuda_bf16.h>
#include <cstdint>

// Problem constants
#define BATCH 4
#define SEQ   2048
#define EMB   256
#define HEADS 8
#define HDIM  32
#define FFN   1024
#define NTOK  (BATCH * SEQ)   // 8192
#define K3E   (3 * EMB)       // 768 : split K for E-dim GEMMs
#define K3F   (3 * FFN)       // 3072: split K for FFN2

// ---------------- scratch (no allocations allowed) ----------------
static __device__ float g_qkv [NTOK * K3E];          // qkv fp32 [8192,768]
static __device__ float g_src2[NTOK * EMB];          // src + attn@w_out^T
static __device__ __nv_bfloat16 g_xs  [NTOK * K3E];  // split LN1 out   (A-style: hi,lo,hi)
static __device__ __nv_bfloat16 g_atts[NTOK * K3E];  // split attn out  (A-style)
static __device__ __nv_bfloat16 g_ys  [NTOK * K3E];  // split LN2 out   (A-style)
static __device__ __nv_bfloat16 g_hs  [NTOK * K3F];  // split relu(ffn1)(A-style)
static __device__ __nv_bfloat16 g_wsin [768  * K3E]; // split weights   (B-style: hi,hi,lo)
static __device__ __nv_bfloat16 g_wsout[256  * K3E];
static __device__ __nv_bfloat16 g_w1s  [1024 * K3E];
static __device__ __nv_bfloat16 g_w2s  [256  * K3F];

// ---------------- helpers ----------------
__device__ __forceinline__ uint32_t smem_u32(const void* p) {
    uint32_t a;
    asm("{ .reg .u64 t; cvta.to.shared.u64 t, %1; cvt.u32.u64 %0, t; }" : "=r"(a) : "l"(p));
    return a;
}
__device__ __forceinline__ void cp_async16(uint32_t saddr, const void* gaddr) {
    asm volatile("cp.async.cg.shared.global [%0], [%1], 16;" :: "r"(saddr), "l"(gaddr));
}
__device__ __forceinline__ void cp_commit() {
    asm volatile("cp.async.commit_group;");
}
template<int N>
__device__ __forceinline__ void cp_wait() {
    asm volatile("cp.async.wait_group %0;" :: "n"(N));
}
__device__ __forceinline__ void ldsm_x4(uint32_t* r, uint32_t addr) {
    asm volatile("ldmatrix.sync.aligned.m8n8.x4.shared.b16 {%0,%1,%2,%3}, [%4];"
                 : "=r"(r[0]), "=r"(r[1]), "=r"(r[2]), "=r"(r[3]) : "r"(addr));
}
__device__ __forceinline__ void ldsm_x4_t(uint32_t* r, uint32_t addr) {
    asm volatile("ldmatrix.sync.aligned.m8n8.x4.trans.shared.b16 {%0,%1,%2,%3}, [%4];"
                 : "=r"(r[0]), "=r"(r[1]), "=r"(r[2]), "=r"(r[3]) : "r"(addr));
}
__device__ __forceinline__ void mma16816(float* c, const uint32_t* a, uint32_t b0, uint32_t b1) {
    asm volatile("mma.sync.aligned.m16n8k16.row.col.f32.bf16.bf16.f32 "
                 "{%0,%1,%2,%3}, {%4,%5,%6,%7}, {%8,%9}, {%0,%1,%2,%3};"
                 : "+f"(c[0]), "+f"(c[1]), "+f"(c[2]), "+f"(c[3])
                 : "r"(a[0]), "r"(a[1]), "r"(a[2]), "r"(a[3]), "r"(b0), "r"(b1));
}
__device__ __forceinline__ float fast_exp2(float x) {
    float y; asm("ex2.approx.ftz.f32 %0, %1;" : "=f"(y) : "f"(x)); return y;
}
__device__ __forceinline__ uint32_t pack_bf16(float lo, float hi) {
    uint32_t r;
    asm("cvt.rn.bf16x2.f32 %0, %1, %2;" : "=r"(r) : "f"(hi), "f"(lo));
    return r;
}
__device__ __forceinline__ void split1(float v, __nv_bfloat16& h, __nv_bfloat16& l) {
    h = __float2bfloat16(v);
    l = __float2bfloat16(v - __bfloat162float(h));
}
// write float4 as (hi,lo,hi) into a 3*256-wide bf16 row at column `col`
__device__ __forceinline__ void split_store4_256(__nv_bfloat16* rowbase, int col, float4 v) {
    __nv_bfloat16 hx, lx, hy, ly, hz, lz, hw, lw;
    split1(v.x, hx, lx); split1(v.y, hy, ly); split1(v.z, hz, lz); split1(v.w, hw, lw);
    *(__nv_bfloat162*)(rowbase + col)           = __halves2bfloat162(hx, hy);
    *(__nv_bfloat162*)(rowbase + col + 2)       = __halves2bfloat162(hz, hw);
    *(__nv_bfloat162*)(rowbase + 256 + col)     = __halves2bfloat162(lx, ly);
    *(__nv_bfloat162*)(rowbase + 256 + col + 2) = __halves2bfloat162(lz, lw);
    *(__nv_bfloat162*)(rowbase + 512 + col)     = __halves2bfloat162(hx, hy);
    *(__nv_bfloat162*)(rowbase + 512 + col + 2) = __halves2bfloat162(hz, hw);
}

// ---------------- LayerNorm -> split bf16 (A-style), one warp per token ----------------
__global__ void ln_split_kernel(const float* __restrict__ in,
                                const float* __restrict__ gamma,
                                const float* __restrict__ beta,
                                __nv_bfloat16* __restrict__ out3) {
    int warp = threadIdx.x >> 5;
    int lane = threadIdx.x & 31;
    int token = blockIdx.x * 8 + warp;
    const float4* row = (const float4*)(in + (size_t)token * EMB);
    float4 v0 = row[lane];
    float4 v1 = row[lane + 32];
    float sum = (v0.x + v0.y) + (v0.z + v0.w) + (v1.x + v1.y) + (v1.z + v1.w);
    float sq  = v0.x*v0.x + v0.y*v0.y + v0.z*v0.z + v0.w*v0.w
              + v1.x*v1.x + v1.y*v1.y + v1.z*v1.z + v1.w*v1.w;
    #pragma unroll
    for (int off = 16; off > 0; off >>= 1) {
        sum += __shfl_xor_sync(0xffffffffu, sum, off);
        sq  += __shfl_xor_sync(0xffffffffu, sq,  off);
    }
    float mu  = sum * (1.0f / EMB);
    float var = sq * (1.0f / EMB) - mu * mu;
    float rs  = rsqrtf(var + 1e-5f);

    const float4* g4 = (const float4*)gamma;
    const float4* b4 = (const float4*)beta;
    float4 ga = g4[lane], gb = g4[lane + 32];
    float4 ba = b4[lane], bb = b4[lane + 32];
    float4 o0, o1;
    o0.x = (v0.x - mu) * rs * ga.x + ba.x;
    o0.y = (v0.y - mu) * rs * ga.y + ba.y;
    o0.z = (v0.z - mu) * rs * ga.z + ba.z;
    o0.w = (v0.w - mu) * rs * ga.w + ba.w;
    o1.x = (v1.x - mu) * rs * gb.x + bb.x;
    o1.y = (v1.y - mu) * rs * gb.y + bb.y;
    o1.z = (v1.z - mu) * rs * gb.z + bb.z;
    o1.w = (v1.w - mu) * rs * gb.w + bb.w;
    __nv_bfloat16* rb = out3 + (size_t)token * K3E;
    split_store4_256(rb, lane * 4, o0);
    split_store4_256(rb, 128 + lane * 4, o1);
}

// ---------------- weight split: [N,K] fp32 -> [N,3K] bf16 (B-style: hi,hi,lo) ----------------
__global__ void split_w_kernel(const float* __restrict__ w, __nv_bfloat16* __restrict__ out,
                               int NK, int K) {
    int i = blockIdx.x * 256 + threadIdx.x;
    if (i >= NK) return;
    int r = i / K, c = i - r * K;
    float v = w[i];
    __nv_bfloat16 h, l;
    split1(v, h, l);
    size_t base = (size_t)r * 3 * K;
    out[base + c]         = h;
    out[base + K + c]     = h;
    out[base + 2 * K + c] = l;
}

// ---------------- mma.sync split-bf16 GEMM ----------------
// C[M,N] = A''[M,K3] * B''[N,K3]^T  (bf16 HMMA, fp32 accum)
// CTA tile 128x128, BK=64 bf16 (128B swizzled rows), 2-stage cp.async pipeline.
// 8 warps in 2x4: warp tile 64x32 (4 m16 x 4 n8).
// EPI: 0=plain fp32, 1=+resid fp32, 2=+bias,relu -> split bf16 (NS-wide), 3=+bias,+resid fp32
#define STAGE_BYTES 32768       // 16KB A + 16KB B
template<int EPI>
__global__ void __launch_bounds__(256)
gemm_mma_kernel(const __nv_bfloat16* __restrict__ A, const __nv_bfloat16* __restrict__ B,
                const float* __restrict__ bias, const float* __restrict__ resid,
                float* __restrict__ outF, __nv_bfloat16* __restrict__ outS,
                int K3, int N, int NS) {
    extern __shared__ char smem[];
    const int tid  = threadIdx.x;
    const int wid  = tid >> 5;
    const int lane = tid & 31;
    const int m0 = blockIdx.y * 128;
    const int n0 = blockIdx.x * 128;
    const int wm = (wid >> 2) * 64;   // warp M offset
    const int wn = (wid & 3) * 32;    // warp N offset
    const uint32_t sbase = smem_u32(smem);
    const size_t rbytes = (size_t)K3 * 2;

    float acc[4][4][4];
    #pragma unroll
    for (int i = 0; i < 4; i++)
        #pragma unroll
        for (int j = 0; j < 4; j++)
            #pragma unroll
            for (int r = 0; r < 4; r++) acc[i][j][r] = 0.f;

    const int lrow = tid >> 3;          // 0..31
    const int lcol = (tid & 7) * 16;    // byte within 128B row
    const char* gA0 = (const char*)A + (size_t)m0 * rbytes;
    const char* gB0 = (const char*)B + (size_t)n0 * rbytes;

    const int nchunk = K3 >> 6;

    auto issue = [&](int c, int s) {
        uint32_t sA = sbase + s * STAGE_BYTES;
        uint32_t sB = sA + 16384;
        const char* gA = gA0 + (size_t)c * 128;
        const char* gB = gB0 + (size_t)c * 128;
        #pragma unroll
        for (int i = 0; i < 4; i++) {
            int r = lrow + i * 32;
            int so = r * 128 + lcol;
            so ^= (so >> 3) & 0x70;
            cp_async16(sA + so, gA + (size_t)r * rbytes + lcol);
            cp_async16(sB + so, gB + (size_t)r * rbytes + lcol);
        }
        cp_commit();
    };

    issue(0, 0);
    for (int c = 0; c < nchunk; ++c) {
        int s = c & 1;
        if (c + 1 < nchunk) { issue(c + 1, s ^ 1); cp_wait<1>(); }
        else               { cp_wait<0>(); }
        __syncthreads();

        uint32_t sA = sbase + s * STAGE_BYTES;
        uint32_t sB = sA + 16384;
        #pragma unroll
        for (int k16 = 0; k16 < 4; ++k16) {
            uint32_t af[4][4];
            #pragma unroll
            for (int mi = 0; mi < 4; ++mi) {
                int row = wm + mi * 16 + (lane & 15);
                int col = k16 * 32 + ((lane >> 4) << 4);
                int so = row * 128 + col;
                so ^= (so >> 3) & 0x70;
                ldsm_x4(af[mi], sA + so);
            }
            uint32_t bf[2][4];
            #pragma unroll
            for (int nb = 0; nb < 2; ++nb) {
                int grp = lane >> 3;
                int row = wn + nb * 16 + ((grp >> 1) << 3) + (lane & 7);
                int col = k16 * 32 + ((grp & 1) << 4);
                int so = row * 128 + col;
                so ^= (so >> 3) & 0x70;
                ldsm_x4(bf[nb], sB + so);
            }
            #pragma unroll
            for (int mi = 0; mi < 4; ++mi)
                #pragma unroll
                for (int nj = 0; nj < 4; ++nj)
                    mma16816(acc[mi][nj], af[mi],
                             bf[nj >> 1][(nj & 1) * 2], bf[nj >> 1][(nj & 1) * 2 + 1]);
        }
        __syncthreads();
    }

    // ---------------- epilogue ----------------
    #pragma unroll
    for (int mi = 0; mi < 4; ++mi) {
        #pragma unroll
        for (int nj = 0; nj < 4; ++nj) {
            int row = m0 + wm + mi * 16 + (lane >> 2);
            int col = n0 + wn + nj * 8 + ((lane & 3) << 1);
            float v0 = acc[mi][nj][0], v1 = acc[mi][nj][1];
            float v2 = acc[mi][nj][2], v3 = acc[mi][nj][3];
            if (EPI == 0) {
                *(float2*)&outF[(size_t)row * N + col]       = make_float2(v0, v1);
                *(float2*)&outF[(size_t)(row + 8) * N + col] = make_float2(v2, v3);
            } else if (EPI == 1) {
                float2 r0 = *(const float2*)&resid[(size_t)row * N + col];
                float2 r1 = *(const float2*)&resid[(size_t)(row + 8) * N + col];
                *(float2*)&outF[(size_t)row * N + col]       = make_float2(v0 + r0.x, v1 + r0.y);
                *(float2*)&outF[(size_t)(row + 8) * N + col] = make_float2(v2 + r1.x, v3 + r1.y);
            } else if (EPI == 3) {
                float2 bv = *(const float2*)&bias[col];
                float2 r0 = *(const float2*)&resid[(size_t)row * N + col];
                float2 r1 = *(const float2*)&resid[(size_t)(row + 8) * N + col];
                *(float2*)&outF[(size_t)row * N + col]       = make_float2(v0 + bv.x + r0.x, v1 + bv.y + r0.y);
                *(float2*)&outF[(size_t)(row + 8) * N + col] = make_float2(v2 + bv.x + r1.x, v3 + bv.y + r1.y);
            } else { // EPI == 2: bias + relu -> split bf16 (hi,lo,hi), NS-wide segments
                float2 bv = *(const float2*)&bias[col];
                float a0 = fmaxf(v0 + bv.x, 0.f), a1 = fmaxf(v1 + bv.y, 0.f);
                float a2 = fmaxf(v2 + bv.x, 0.f), a3 = fmaxf(v3 + bv.y, 0.f);
                __nv_bfloat16 h0,l0,h1,l1,h2,l2,h3,l3;
                split1(a0,h0,l0); split1(a1,h1,l1); split1(a2,h2,l2); split1(a3,h3,l3);
                __nv_bfloat16* r0b = outS + (size_t)row * 3 * NS;
                __nv_bfloat16* r1b = outS + (size_t)(row + 8) * 3 * NS;
                *(__nv_bfloat162*)(r0b + col)          = __halves2bfloat162(h0, h1);
                *(__nv_bfloat162*)(r0b + NS + col)     = __halves2bfloat162(l0, l1);
                *(__nv_bfloat162*)(r0b + 2 * NS + col) = __halves2bfloat162(h0, h1);
                *(__nv_bfloat162*)(r1b + col)          = __halves2bfloat162(h2, h3);
                *(__nv_bfloat162*)(r1b + NS + col)     = __halves2bfloat162(l2, l3);
                *(__nv_bfloat162*)(r1b + 2 * NS + col) = __halves2bfloat162(h2, h3);
            }
        }
    }
}

// ---------------- Attention: mma.sync flash attention ----------------
// CTA: 128 queries (8 warps x m16), K-tile = 64 keys, D=32, bf16 HMMA.
// SMEM tiles stride 40 bf16 (80B) for conflict-free ldmatrix.
#define AT_STRIDE 40
__global__ void __launch_bounds__(256)
attn_mma_kernel(const float* __restrict__ qkv, __nv_bfloat16* __restrict__ att3) {
    __shared__ __nv_bfloat16 Qs[128 * AT_STRIDE];
    __shared__ __nv_bfloat16 Ks[64 * AT_STRIDE];
    __shared__ __nv_bfloat16 Vs[64 * AT_STRIDE];

    const int tid  = threadIdx.x;
    const int wid  = tid >> 5;
    const int lane = tid & 31;
    const int b = blockIdx.y >> 3;
    const int h = blockIdx.y & 7;
    const int q0 = blockIdx.x * 128;
    const float scale2 = 0.17677669529663687f * 1.4426950408889634f; // 1/sqrt(32)*log2(e)

    // ---- stage Q (scaled) ----
    {
        int row = tid >> 1;
        int d0  = (tid & 1) * 16;
        const float2* g = (const float2*)(qkv + (size_t)(b * SEQ + q0 + row) * K3E + h * HDIM + d0);
        #pragma unroll
        for (int i = 0; i < 8; ++i) {
            float2 v = g[i];
            *(uint32_t*)&Qs[row * AT_STRIDE + d0 + 2 * i] = pack_bf16(v.x * scale2, v.y * scale2);
        }
    }
    __syncthreads();

    // ---- load Q fragments (m16k16 x2) ----
    uint32_t qsb = smem_u32(Qs), ksb = smem_u32(Ks), vsb = smem_u32(Vs);
    uint32_t qf[2][4];
    #pragma unroll
    for (int kc = 0; kc < 2; ++kc) {
        int row = wid * 16 + (lane & 15);
        int colb = kc * 32 + ((lane >> 4) << 4);
        ldsm_x4(qf[kc], qsb + row * (AT_STRIDE * 2) + colb);
    }

    float oacc[4][4];
    #pragma unroll
    for (int j = 0; j < 4; ++j)
        #pragma unroll
        for (int r = 0; r < 4; ++r) oacc[j][r] = 0.f;
    float m0r = -1e30f, m1r = -1e30f, l0 = 0.f, l1 = 0.f;

    const int skey = tid >> 2;           // 0..63
    const int sd0  = (tid & 3) * 8;      // 0,8,16,24

    for (int k0 = 0; k0 < SEQ; k0 += 64) {
        __syncthreads();
        // ---- stage K, V (fp32 -> bf16) ----
        {
            const float2* gk = (const float2*)(qkv + (size_t)(b * SEQ + k0 + skey) * K3E + EMB     + h * HDIM + sd0);
            const float2* gv = (const float2*)(qkv + (size_t)(b * SEQ + k0 + skey) * K3E + 2 * EMB + h * HDIM + sd0);
            #pragma unroll
            for (int i = 0; i < 4; ++i) {
                float2 kv = gk[i], vv = gv[i];
                *(uint32_t*)&Ks[skey * AT_STRIDE + sd0 + 2 * i] = pack_bf16(kv.x, kv.y);
                *(uint32_t*)&Vs[skey * AT_STRIDE + sd0 + 2 * i] = pack_bf16(vv.x, vv.y);
            }
        }
        __syncthreads();

        // ---- scores: S[16q x 64k] ----
        float sc[8][4];
        #pragma unroll
        for (int nj = 0; nj < 8; ++nj)
            #pragma unroll
            for (int r = 0; r < 4; ++r) sc[nj][r] = 0.f;

        #pragma unroll
        for (int kc = 0; kc < 2; ++kc) {
            uint32_t kb[4][4];
            #pragma unroll
            for (int nb = 0; nb < 4; ++nb) {
                int grp = lane >> 3;
                int row = nb * 16 + ((grp >> 1) << 3) + (lane & 7);
                int colb = kc * 32 + ((grp & 1) << 4);
                ldsm_x4(kb[nb], ksb + row * (AT_STRIDE * 2) + colb);
            }
            #pragma unroll
            for (int nj = 0; nj < 8; ++nj)
                mma16816(sc[nj], qf[kc], kb[nj >> 1][(nj & 1) * 2], kb[nj >> 1][(nj & 1) * 2 + 1]);
        }

        // ---- online softmax ----
        float tm0 = -1e30f, tm1 = -1e30f;
        #pragma unroll
        for (int nj = 0; nj < 8; ++nj) {
            tm0 = fmaxf(tm0, fmaxf(sc[nj][0], sc[nj][1]));
            tm1 = fmaxf(tm1, fmaxf(sc[nj][2], sc[nj][3]));
        }
        tm0 = fmaxf(tm0, __shfl_xor_sync(0xffffffffu, tm0, 1));
        tm0 = fmaxf(tm0, __shfl_xor_sync(0xffffffffu, tm0, 2));
        tm1 = fmaxf(tm1, __shfl_xor_sync(0xffffffffu, tm1, 1));
        tm1 = fmaxf(tm1, __shfl_xor_sync(0xffffffffu, tm1, 2));
        float nm0 = fmaxf(m0r, tm0), nm1 = fmaxf(m1r, tm1);
        float c0 = fast_exp2(m0r - nm0), c1 = fast_exp2(m1r - nm1);
        m0r = nm0; m1r = nm1;

        float s0 = 0.f, s1 = 0.f;
        #pragma unroll
        for (int nj = 0; nj < 8; ++nj) {
            sc[nj][0] = fast_exp2(sc[nj][0] - nm0);
            sc[nj][1] = fast_exp2(sc[nj][1] - nm0);
            sc[nj][2] = fast_exp2(sc[nj][2] - nm1);
            sc[nj][3] = fast_exp2(sc[nj][3] - nm1);
            s0 += sc[nj][0] + sc[nj][1];
            s1 += sc[nj][2] + sc[nj][3];
        }
        s0 += __shfl_xor_sync(0xffffffffu, s0, 1);
        s0 += __shfl_xor_sync(0xffffffffu, s0, 2);
        s1 += __shfl_xor_sync(0xffffffffu, s1, 1);
        s1 += __shfl_xor_sync(0xffffffffu, s1, 2);
        l0 = l0 * c0 + s0;
        l1 = l1 * c1 + s1;
        #pragma unroll
        for (int j = 0; j < 4; ++j) {
            oacc[j][0] *= c0; oacc[j][1] *= c0;
            oacc[j][2] *= c1; oacc[j][3] *= c1;
        }

        // ---- pack P into A fragments (C->A identity) ----
        uint32_t a[4][4];
        #pragma unroll
        for (int kc = 0; kc < 4; ++kc) {
            a[kc][0] = pack_bf16(sc[2 * kc][0],     sc[2 * kc][1]);
            a[kc][1] = pack_bf16(sc[2 * kc][2],     sc[2 * kc][3]);
            a[kc][2] = pack_bf16(sc[2 * kc + 1][0], sc[2 * kc + 1][1]);
            a[kc][3] = pack_bf16(sc[2 * kc + 1][2], sc[2 * kc + 1][3]);
        }

        // ---- P @ V ----
        #pragma unroll
        for (int kc = 0; kc < 4; ++kc) {
            uint32_t vb[2][4];
            #pragma unroll
            for (int half = 0; half < 2; ++half) {
                int grp = lane >> 3;
                int row = kc * 16 + ((grp & 1) << 3) + (lane & 7);
                int colb = half * 32 + ((grp >> 1) << 4);
                ldsm_x4_t(vb[half], vsb + row * (AT_STRIDE * 2) + colb);
            }
            #pragma unroll
            for (int dj = 0; dj < 4; ++dj)
                mma16816(oacc[dj], a[kc], vb[dj >> 1][(dj & 1) * 2], vb[dj >> 1][(dj & 1) * 2 + 1]);
        }
    }

    // ---- epilogue: normalize, split-store bf16 (hi,lo,hi) ----
    float inv0 = 1.0f / l0, inv1 = 1.0f / l1;
    int r0 = q0 + wid * 16 + (lane >> 2);
    __nv_bfloat16* rb0 = att3 + (size_t)(b * SEQ + r0) * K3E;
    __nv_bfloat16* rb1 = att3 + (size_t)(b * SEQ + r0 + 8) * K3E;
    #pragma unroll
    for (int dj = 0; dj < 4; ++dj) {
        int col = h * HDIM + dj * 8 + ((lane & 3) << 1);
        float v0 = oacc[dj][0] * inv0, v1 = oacc[dj][1] * inv0;
        float v2 = oacc[dj][2] * inv1, v3 = oacc[dj][3] * inv1;
        __nv_bfloat16 h0,lo0,h1,lo1,h2,lo2,h3,lo3;
        split1(v0,h0,lo0); split1(v1,h1,lo1); split1(v2,h2,lo2); split1(v3,h3,lo3);
        *(__nv_bfloat162*)(rb0 + col)       = __halves2bfloat162(h0, h1);
        *(__nv_bfloat162*)(rb0 + 256 + col) = __halves2bfloat162(lo0, lo1);
        *(__nv_bfloat162*)(rb0 + 512 + col) = __halves2bfloat162(h0, h1);
        *(__nv_bfloat162*)(rb1 + col)       = __halves2bfloat162(h2, h3);
        *(__nv_bfloat162*)(rb1 + 256 + col) = __halves2bfloat162(lo2, lo3);
        *(__nv_bfloat162*)(rb1 + 512 + col) = __halves2bfloat162(h2, h3);
    }
}

// ---------------- launcher ----------------
extern "C" void kernel_launch(void* const* d_in, const int* in_sizes, int n_in,
                              void* d_out, int out_size) {
    const float* src   = (const float*)d_in[0];
    const float* w_in  = (const float*)d_in[1];
    const float* w_out = (const float*)d_in[2];
    const float* w1    = (const float*)d_in[3];
    const float* b1    = (const float*)d_in[4];
    const float* w2    = (const float*)d_in[5];
    const float* b2    = (const float*)d_in[6];
    const float* g1    = (const float*)d_in[7];
    const float* be1   = (const float*)d_in[8];
    const float* g2    = (const float*)d_in[9];
    const float* be2   = (const float*)d_in[10];
    float* out = (float*)d_out;

    float *qkv, *src2;
    __nv_bfloat16 *xs, *atts, *ys, *hs, *wsin, *wsout, *w1s, *w2s;
    cudaGetSymbolAddress((void**)&qkv,   g_qkv);
    cudaGetSymbolAddress((void**)&src2,  g_src2);
    cudaGetSymbolAddress((void**)&xs,    g_xs);
    cudaGetSymbolAddress((void**)&atts,  g_atts);
    cudaGetSymbolAddress((void**)&ys,    g_ys);
    cudaGetSymbolAddress((void**)&hs,    g_hs);
    cudaGetSymbolAddress((void**)&wsin,  g_wsin);
    cudaGetSymbolAddress((void**)&wsout, g_wsout);
    cudaGetSymbolAddress((void**)&w1s,   g_w1s);
    cudaGetSymbolAddress((void**)&w2s,   g_w2s);

    const int SMEM = 2 * STAGE_BYTES;   // 64KB
    cudaFuncSetAttribute(gemm_mma_kernel<0>, cudaFuncAttributeMaxDynamicSharedMemorySize, SMEM);
    cudaFuncSetAttribute(gemm_mma_kernel<1>, cudaFuncAttributeMaxDynamicSharedMemorySize, SMEM);
    cudaFuncSetAttribute(gemm_mma_kernel<2>, cudaFuncAttributeMaxDynamicSharedMemorySize, SMEM);
    cudaFuncSetAttribute(gemm_mma_kernel<3>, cudaFuncAttributeMaxDynamicSharedMemorySize, SMEM);

    // weight splits (B-style)
    split_w_kernel<<<(768 * 256 + 255) / 256, 256>>>(w_in,  wsin,  768 * 256, 256);
    split_w_kernel<<<(256 * 256 + 255) / 256, 256>>>(w_out, wsout, 256 * 256, 256);
    split_w_kernel<<<(1024 * 256 + 255) / 256, 256>>>(w1,   w1s,  1024 * 256, 256);
    split_w_kernel<<<(256 * 1024 + 255) / 256, 256>>>(w2,   w2s,  256 * 1024, 1024);

    // 1) xs = split(LN1(src))
    ln_split_kernel<<<NTOK / 8, 256>>>(src, g1, be1, xs);
    // 2) qkv = xs @ wsin^T   [8192,768] fp32
    gemm_mma_kernel<0><<<dim3(768 / 128, NTOK / 128), 256, SMEM>>>(
        xs, wsin, nullptr, nullptr, qkv, nullptr, K3E, 768, 0);
    // 3) atts = split(softmax(qk^T)v)   (tensor-core flash attention)
    attn_mma_kernel<<<dim3(SEQ / 128, BATCH * HEADS), 256>>>(qkv, atts);
    // 4) src2 = src + atts @ wsout^T
    gemm_mma_kernel<1><<<dim3(256 / 128, NTOK / 128), 256, SMEM>>>(
        atts, wsout, nullptr, src, src2, nullptr, K3E, 256, 0);
    // 5) ys = split(LN2(src2))
    ln_split_kernel<<<NTOK / 8, 256>>>(src2, g2, be2, ys);
    // 6) hs = split(relu(ys @ w1s^T + b1))
    gemm_mma_kernel<2><<<dim3(1024 / 128, NTOK / 128), 256, SMEM>>>(
        ys, w1s, b1, nullptr, nullptr, hs, K3E, 1024, FFN);
    // 7) out = src2 + hs @ w2s^T + b2
    gemm_mma_kernel<3><<<dim3(256 / 128, NTOK / 128), 256, SMEM>>>(
        hs, w2s, b2, src2, out, nullptr, K3F, 256, 0);
}

// round 5
// speedup vs baseline: 6.0775x; 1.5982x over previous
#include <cuda_runtime.h>
#include <cuda_bf16.h>
#include <cuda_fp16.h>
#include <cstdint>

// Problem constants
#define BATCH 4
#define SEQ   2048
#define EMB   256
#define HEADS 8
#define HDIM  32
#define FFN   1024
#define NTOK  (BATCH * SEQ)   // 8192

// ---------------- scratch (no allocations allowed) ----------------
static __device__ float  g_src2[NTOK * EMB];            // src + attn@w_out^T (fp32)
static __device__ __half g_xs [NTOK * EMB];             // LN1 out fp16
static __device__ __half g_att[NTOK * EMB];             // attention out fp16
static __device__ __half g_ys [NTOK * EMB];             // LN2 out fp16
static __device__ __half g_hh [NTOK * FFN];             // relu(ffn1) fp16
static __device__ __nv_bfloat16 g_q[NTOK * EMB];        // per-head [bh][s][d], q pre-scaled
static __device__ __nv_bfloat16 g_k[NTOK * EMB];
static __device__ __nv_bfloat16 g_v[NTOK * EMB];
static __device__ __half g_wsin [768  * 2 * EMB];       // weights [N, 2K] = [hi | lo]
static __device__ __half g_wsout[256  * 2 * EMB];
static __device__ __half g_w1s  [1024 * 2 * EMB];
static __device__ __half g_w2s  [256  * 2 * FFN];

// ---------------- helpers ----------------
__device__ __forceinline__ uint32_t smem_u32(const void* p) {
    uint32_t a;
    asm("{ .reg .u64 t; cvta.to.shared.u64 t, %1; cvt.u32.u64 %0, t; }" : "=r"(a) : "l"(p));
    return a;
}
__device__ __forceinline__ void cp_async16(uint32_t saddr, const void* gaddr) {
    asm volatile("cp.async.cg.shared.global [%0], [%1], 16;" :: "r"(saddr), "l"(gaddr));
}
__device__ __forceinline__ void cp_commit() {
    asm volatile("cp.async.commit_group;");
}
template<int N>
__device__ __forceinline__ void cp_wait() {
    asm volatile("cp.async.wait_group %0;" :: "n"(N));
}
__device__ __forceinline__ void ldsm_x4(uint32_t* r, uint32_t addr) {
    asm volatile("ldmatrix.sync.aligned.m8n8.x4.shared.b16 {%0,%1,%2,%3}, [%4];"
                 : "=r"(r[0]), "=r"(r[1]), "=r"(r[2]), "=r"(r[3]) : "r"(addr));
}
__device__ __forceinline__ void ldsm_x4_t(uint32_t* r, uint32_t addr) {
    asm volatile("ldmatrix.sync.aligned.m8n8.x4.trans.shared.b16 {%0,%1,%2,%3}, [%4];"
                 : "=r"(r[0]), "=r"(r[1]), "=r"(r[2]), "=r"(r[3]) : "r"(addr));
}
__device__ __forceinline__ void mma_bf16(float* c, const uint32_t* a, uint32_t b0, uint32_t b1) {
    asm volatile("mma.sync.aligned.m16n8k16.row.col.f32.bf16.bf16.f32 "
                 "{%0,%1,%2,%3}, {%4,%5,%6,%7}, {%8,%9}, {%0,%1,%2,%3};"
                 : "+f"(c[0]), "+f"(c[1]), "+f"(c[2]), "+f"(c[3])
                 : "r"(a[0]), "r"(a[1]), "r"(a[2]), "r"(a[3]), "r"(b0), "r"(b1));
}
__device__ __forceinline__ void mma_f16(float* c, const uint32_t* a, uint32_t b0, uint32_t b1) {
    asm volatile("mma.sync.aligned.m16n8k16.row.col.f32.f16.f16.f32 "
                 "{%0,%1,%2,%3}, {%4,%5,%6,%7}, {%8,%9}, {%0,%1,%2,%3};"
                 : "+f"(c[0]), "+f"(c[1]), "+f"(c[2]), "+f"(c[3])
                 : "r"(a[0]), "r"(a[1]), "r"(a[2]), "r"(a[3]), "r"(b0), "r"(b1));
}
__device__ __forceinline__ float fast_exp2(float x) {
    float y; asm("ex2.approx.ftz.f32 %0, %1;" : "=f"(y) : "f"(x)); return y;
}
__device__ __forceinline__ uint32_t pack_bf16(float lo, float hi) {
    uint32_t r;
    asm("cvt.rn.bf16x2.f32 %0, %1, %2;" : "=r"(r) : "f"(hi), "f"(lo));
    return r;
}
__device__ __forceinline__ uint32_t pack_f16(float lo, float hi) {
    uint32_t r;
    asm("cvt.rn.f16x2.f32 %0, %1, %2;" : "=r"(r) : "f"(hi), "f"(lo));
    return r;
}

// ---------------- LayerNorm -> fp16, one warp per token ----------------
__global__ void ln_f16_kernel(const float* __restrict__ in,
                              const float* __restrict__ gamma,
                              const float* __restrict__ beta,
                              __half* __restrict__ out) {
    int warp = threadIdx.x >> 5;
    int lane = threadIdx.x & 31;
    int token = blockIdx.x * 8 + warp;
    const float4* row = (const float4*)(in + (size_t)token * EMB);
    float4 v0 = row[lane];
    float4 v1 = row[lane + 32];
    float sum = (v0.x + v0.y) + (v0.z + v0.w) + (v1.x + v1.y) + (v1.z + v1.w);
    float sq  = v0.x*v0.x + v0.y*v0.y + v0.z*v0.z + v0.w*v0.w
              + v1.x*v1.x + v1.y*v1.y + v1.z*v1.z + v1.w*v1.w;
    #pragma unroll
    for (int off = 16; off > 0; off >>= 1) {
        sum += __shfl_xor_sync(0xffffffffu, sum, off);
        sq  += __shfl_xor_sync(0xffffffffu, sq,  off);
    }
    float mu  = sum * (1.0f / EMB);
    float var = sq * (1.0f / EMB) - mu * mu;
    float rs  = rsqrtf(var + 1e-5f);

    const float4* g4 = (const float4*)gamma;
    const float4* b4 = (const float4*)beta;
    float4 ga = g4[lane], gb = g4[lane + 32];
    float4 ba = b4[lane], bb = b4[lane + 32];
    uint2 o0, o1;
    o0.x = pack_f16((v0.x - mu) * rs * ga.x + ba.x, (v0.y - mu) * rs * ga.y + ba.y);
    o0.y = pack_f16((v0.z - mu) * rs * ga.z + ba.z, (v0.w - mu) * rs * ga.w + ba.w);
    o1.x = pack_f16((v1.x - mu) * rs * gb.x + bb.x, (v1.y - mu) * rs * gb.y + bb.y);
    o1.y = pack_f16((v1.z - mu) * rs * gb.z + bb.z, (v1.w - mu) * rs * gb.w + bb.w);
    *(uint2*)(out + (size_t)token * EMB + lane * 4)       = o0;
    *(uint2*)(out + (size_t)token * EMB + 128 + lane * 4) = o1;
}

// ---------------- fused weight split: fp32 [N,K] -> fp16 [N,2K] = [hi|lo] ----------------
__global__ void split_w_all(const float* __restrict__ w_in, const float* __restrict__ w_out,
                            const float* __restrict__ w1, const float* __restrict__ w2,
                            __half* __restrict__ wsin, __half* __restrict__ wsout,
                            __half* __restrict__ w1s, __half* __restrict__ w2s) {
    int blk = blockIdx.x;
    const float* src;
    __half* dst;
    int K, lb;
    if (blk < 768)       { src = w_in;  dst = wsin;  K = 256;  lb = blk; }
    else if (blk < 1024) { src = w_out; dst = wsout; K = 256;  lb = blk - 768; }
    else if (blk < 2048) { src = w1;    dst = w1s;   K = 256;  lb = blk - 1024; }
    else                 { src = w2;    dst = w2s;   K = 1024; lb = blk - 2048; }
    int i = lb * 256 + threadIdx.x;
    int r = i / K, c = i - r * K;
    float vv = src[i];
    __half h = __float2half_rn(vv);
    __half l = __float2half_rn(vv - __half2float(h));
    dst[(size_t)r * 2 * K + c]     = h;
    dst[(size_t)r * 2 * K + K + c] = l;
}

// ---------------- fp16 B-compensated GEMM ----------------
// C[M,N] = A[M,K] * (Bhi + Blo)[N,K]^T   (fp16 HMMA, fp32 accum)
// CTA tile 128x128, BK=64. Per stage: A 16KB + Bhi 16KB + Blo 16KB = 48KB, 2 stages.
// 8 warps in 2x4: warp tile 64x32.
// EPI: 0=qkv->bf16 per-head (q scaled), 1=+resid fp32, 2=+bias,relu->fp16, 3=+bias,+resid fp32
#define GSTAGE 49152
template<int EPI>
__global__ void __launch_bounds__(256)
gemm_f16_kernel(const __half* __restrict__ A, const __half* __restrict__ B2,
                const float* __restrict__ bias, const float* __restrict__ resid,
                float* __restrict__ outF, __half* __restrict__ outH,
                __nv_bfloat16* __restrict__ qb, __nv_bfloat16* __restrict__ kb,
                __nv_bfloat16* __restrict__ vb, int K, int N) {
    extern __shared__ char smem[];
    const int tid  = threadIdx.x;
    const int wid  = tid >> 5;
    const int lane = tid & 31;
    const int m0 = blockIdx.y * 128;
    const int n0 = blockIdx.x * 128;
    const int wm = (wid >> 2) * 64;
    const int wn = (wid & 3) * 32;
    const uint32_t sbase = smem_u32(smem);
    const size_t Ab = (size_t)K * 2;      // A row bytes
    const size_t Bb = (size_t)K * 4;      // B2 row bytes (2K halfs)

    float acc[4][4][4];
    #pragma unroll
    for (int i = 0; i < 4; i++)
        #pragma unroll
        for (int j = 0; j < 4; j++)
            #pragma unroll
            for (int r = 0; r < 4; r++) acc[i][j][r] = 0.f;

    const int lrow = tid >> 3;          // 0..31
    const int lcol = (tid & 7) * 16;    // byte within 128B row
    const char* gA0  = (const char*)A  + (size_t)m0 * Ab;
    const char* gBh0 = (const char*)B2 + (size_t)n0 * Bb;
    const char* gBl0 = gBh0 + (size_t)K * 2;    // +K halfs

    const int nchunk = K >> 6;

    auto issue = [&](int c, int s) {
        uint32_t sA  = sbase + s * GSTAGE;
        uint32_t sBh = sA + 16384;
        uint32_t sBl = sA + 32768;
        const char* gA  = gA0  + (size_t)c * 128;
        const char* gBh = gBh0 + (size_t)c * 128;
        const char* gBl = gBl0 + (size_t)c * 128;
        #pragma unroll
        for (int i = 0; i < 4; i++) {
            int r = lrow + i * 32;
            int so = r * 128 + lcol;
            so ^= (so >> 3) & 0x70;
            cp_async16(sA  + so, gA  + (size_t)r * Ab + lcol);
            cp_async16(sBh + so, gBh + (size_t)r * Bb + lcol);
            cp_async16(sBl + so, gBl + (size_t)r * Bb + lcol);
        }
        cp_commit();
    };

    issue(0, 0);
    for (int c = 0; c < nchunk; ++c) {
        int s = c & 1;
        if (c + 1 < nchunk) { issue(c + 1, s ^ 1); cp_wait<1>(); }
        else               { cp_wait<0>(); }
        __syncthreads();

        uint32_t sA  = sbase + s * GSTAGE;
        uint32_t sBh = sA + 16384;
        uint32_t sBl = sA + 32768;
        #pragma unroll
        for (int k16 = 0; k16 < 4; ++k16) {
            uint32_t af[4][4];
            #pragma unroll
            for (int mi = 0; mi < 4; ++mi) {
                int row = wm + mi * 16 + (lane & 15);
                int col = k16 * 32 + ((lane >> 4) << 4);
                int so = row * 128 + col;
                so ^= (so >> 3) & 0x70;
                ldsm_x4(af[mi], sA + so);
            }
            uint32_t bh[2][4], bl[2][4];
            #pragma unroll
            for (int nb = 0; nb < 2; ++nb) {
                int grp = lane >> 3;
                int row = wn + nb * 16 + ((grp >> 1) << 3) + (lane & 7);
                int col = k16 * 32 + ((grp & 1) << 4);
                int so = row * 128 + col;
                so ^= (so >> 3) & 0x70;
                ldsm_x4(bh[nb], sBh + so);
                int so2 = row * 128 + col;
                so2 ^= (so2 >> 3) & 0x70;
                ldsm_x4(bl[nb], sBl + so2);
            }
            #pragma unroll
            for (int mi = 0; mi < 4; ++mi)
                #pragma unroll
                for (int nj = 0; nj < 4; ++nj) {
                    mma_f16(acc[mi][nj], af[mi],
                            bh[nj >> 1][(nj & 1) * 2], bh[nj >> 1][(nj & 1) * 2 + 1]);
                    mma_f16(acc[mi][nj], af[mi],
                            bl[nj >> 1][(nj & 1) * 2], bl[nj >> 1][(nj & 1) * 2 + 1]);
                }
        }
        __syncthreads();
    }

    // ---------------- epilogue ----------------
    const float scale2 = 0.17677669529663687f * 1.4426950408889634f; // 1/sqrt(32)*log2(e)
    #pragma unroll
    for (int mi = 0; mi < 4; ++mi) {
        #pragma unroll
        for (int nj = 0; nj < 4; ++nj) {
            int row = m0 + wm + mi * 16 + (lane >> 2);
            int col = n0 + wn + nj * 8 + ((lane & 3) << 1);
            float v0 = acc[mi][nj][0], v1 = acc[mi][nj][1];
            float v2 = acc[mi][nj][2], v3 = acc[mi][nj][3];
            if (EPI == 0) {
                // qkv -> bf16 per-head layout [(b*8+h)*2048 + s]*32 + d, q scaled
                int part = col >> 8;
                int hh   = (col >> 5) & 7;
                int d    = col & 31;
                int b    = row >> 11, s = row & 2047;
                size_t base0 = ((size_t)(b * 8 + hh) * 2048 + s) * 32 + d;
                size_t base1 = base0 + 8 * 32;
                if (part == 0) {
                    *(uint32_t*)(qb + base0) = pack_bf16(v0 * scale2, v1 * scale2);
                    *(uint32_t*)(qb + base1) = pack_bf16(v2 * scale2, v3 * scale2);
                } else if (part == 1) {
                    *(uint32_t*)(kb + base0) = pack_bf16(v0, v1);
                    *(uint32_t*)(kb + base1) = pack_bf16(v2, v3);
                } else {
                    *(uint32_t*)(vb + base0) = pack_bf16(v0, v1);
                    *(uint32_t*)(vb + base1) = pack_bf16(v2, v3);
                }
            } else if (EPI == 1) {
                float2 r0 = *(const float2*)&resid[(size_t)row * N + col];
                float2 r1 = *(const float2*)&resid[(size_t)(row + 8) * N + col];
                *(float2*)&outF[(size_t)row * N + col]       = make_float2(v0 + r0.x, v1 + r0.y);
                *(float2*)&outF[(size_t)(row + 8) * N + col] = make_float2(v2 + r1.x, v3 + r1.y);
            } else if (EPI == 2) {
                float2 bv = *(const float2*)&bias[col];
                *(uint32_t*)(outH + (size_t)row * N + col) =
                    pack_f16(fmaxf(v0 + bv.x, 0.f), fmaxf(v1 + bv.y, 0.f));
                *(uint32_t*)(outH + (size_t)(row + 8) * N + col) =
                    pack_f16(fmaxf(v2 + bv.x, 0.f), fmaxf(v3 + bv.y, 0.f));
            } else { // EPI == 3
                float2 bv = *(const float2*)&bias[col];
                float2 r0 = *(const float2*)&resid[(size_t)row * N + col];
                float2 r1 = *(const float2*)&resid[(size_t)(row + 8) * N + col];
                *(float2*)&outF[(size_t)row * N + col]       = make_float2(v0 + bv.x + r0.x, v1 + bv.y + r0.y);
                *(float2*)&outF[(size_t)(row + 8) * N + col] = make_float2(v2 + bv.x + r1.x, v3 + bv.y + r1.y);
            }
        }
    }
}

// ---------------- Attention: mma.sync flash attention, bf16 inputs via cp.async ----------------
// CTA: 128 queries (8 warps x m16), K-tile = 64 keys, D=32.
#define AT_STRIDE 40
__global__ void __launch_bounds__(256)
attn_mma_kernel(const __nv_bfloat16* __restrict__ qg, const __nv_bfloat16* __restrict__ kg,
                const __nv_bfloat16* __restrict__ vg, __half* __restrict__ att) {
    __shared__ __nv_bfloat16 Qs[128 * AT_STRIDE];
    __shared__ __nv_bfloat16 Ks[2][64 * AT_STRIDE];
    __shared__ __nv_bfloat16 Vs[2][64 * AT_STRIDE];

    const int tid  = threadIdx.x;
    const int wid  = tid >> 5;
    const int lane = tid & 31;
    const int bh = blockIdx.y;            // b*8 + h
    const int q0 = blockIdx.x * 128;

    uint32_t qsb = smem_u32(Qs);
    uint32_t ksb0 = smem_u32(Ks[0]), ksb1 = smem_u32(Ks[1]);
    uint32_t vsb0 = smem_u32(Vs[0]), vsb1 = smem_u32(Vs[1]);

    // ---- stage Q (group 0) ----
    {
        const char* gq = (const char*)(qg + ((size_t)bh * 2048 + q0) * 32);
        #pragma unroll
        for (int i = 0; i < 2; ++i) {
            int idx = tid + i * 256;
            int row = idx >> 2, c = (idx & 3) * 16;
            cp_async16(qsb + row * (AT_STRIDE * 2) + c, gq + row * 64 + c);
        }
        cp_commit();
    }

    const int srow = tid >> 2;
    const int sc   = (tid & 3) * 16;
    auto issue_kv = [&](int kt, int s) {
        const char* gk = (const char*)(kg + ((size_t)bh * 2048 + kt) * 32);
        const char* gv = (const char*)(vg + ((size_t)bh * 2048 + kt) * 32);
        uint32_t kd = (s ? ksb1 : ksb0) + srow * (AT_STRIDE * 2) + sc;
        uint32_t vd = (s ? vsb1 : vsb0) + srow * (AT_STRIDE * 2) + sc;
        cp_async16(kd, gk + srow * 64 + sc);
        cp_async16(vd, gv + srow * 64 + sc);
        cp_commit();
    };

    issue_kv(0, 0);
    cp_wait<1>();      // Q ready
    __syncthreads();

    // ---- Q fragments ----
    uint32_t qf[2][4];
    #pragma unroll
    for (int kc = 0; kc < 2; ++kc) {
        int row = wid * 16 + (lane & 15);
        int colb = kc * 32 + ((lane >> 4) << 4);
        ldsm_x4(qf[kc], qsb + row * (AT_STRIDE * 2) + colb);
    }

    float oacc[4][4];
    #pragma unroll
    for (int j = 0; j < 4; ++j)
        #pragma unroll
        for (int r = 0; r < 4; ++r) oacc[j][r] = 0.f;
    float m0r = -1e30f, m1r = -1e30f, l0 = 0.f, l1 = 0.f;

    for (int tile = 0; tile < SEQ / 64; ++tile) {
        int s = tile & 1;
        if (tile + 1 < SEQ / 64) { issue_kv((tile + 1) * 64, s ^ 1); cp_wait<1>(); }
        else                     { cp_wait<0>(); }
        __syncthreads();

        uint32_t ksb = s ? ksb1 : ksb0;
        uint32_t vsb = s ? vsb1 : vsb0;

        // ---- scores: S[16q x 64k] ----
        float sc4[8][4];
        #pragma unroll
        for (int nj = 0; nj < 8; ++nj)
            #pragma unroll
            for (int r = 0; r < 4; ++r) sc4[nj][r] = 0.f;

        #pragma unroll
        for (int kc = 0; kc < 2; ++kc) {
            uint32_t kbf[4][4];
            #pragma unroll
            for (int nb = 0; nb < 4; ++nb) {
                int grp = lane >> 3;
                int row = nb * 16 + ((grp >> 1) << 3) + (lane & 7);
                int colb = kc * 32 + ((grp & 1) << 4);
                ldsm_x4(kbf[nb], ksb + row * (AT_STRIDE * 2) + colb);
            }
            #pragma unroll
            for (int nj = 0; nj < 8; ++nj)
                mma_bf16(sc4[nj], qf[kc], kbf[nj >> 1][(nj & 1) * 2], kbf[nj >> 1][(nj & 1) * 2 + 1]);
        }

        // ---- online softmax (base 2) ----
        float tm0 = -1e30f, tm1 = -1e30f;
        #pragma unroll
        for (int nj = 0; nj < 8; ++nj) {
            tm0 = fmaxf(tm0, fmaxf(sc4[nj][0], sc4[nj][1]));
            tm1 = fmaxf(tm1, fmaxf(sc4[nj][2], sc4[nj][3]));
        }
        tm0 = fmaxf(tm0, __shfl_xor_sync(0xffffffffu, tm0, 1));
        tm0 = fmaxf(tm0, __shfl_xor_sync(0xffffffffu, tm0, 2));
        tm1 = fmaxf(tm1, __shfl_xor_sync(0xffffffffu, tm1, 1));
        tm1 = fmaxf(tm1, __shfl_xor_sync(0xffffffffu, tm1, 2));
        float nm0 = fmaxf(m0r, tm0), nm1 = fmaxf(m1r, tm1);
        float c0 = fast_exp2(m0r - nm0), c1 = fast_exp2(m1r - nm1);
        m0r = nm0; m1r = nm1;

        float s0 = 0.f, s1 = 0.f;
        #pragma unroll
        for (int nj = 0; nj < 8; ++nj) {
            sc4[nj][0] = fast_exp2(sc4[nj][0] - nm0);
            sc4[nj][1] = fast_exp2(sc4[nj][1] - nm0);
            sc4[nj][2] = fast_exp2(sc4[nj][2] - nm1);
            sc4[nj][3] = fast_exp2(sc4[nj][3] - nm1);
            s0 += sc4[nj][0] + sc4[nj][1];
            s1 += sc4[nj][2] + sc4[nj][3];
        }
        s0 += __shfl_xor_sync(0xffffffffu, s0, 1);
        s0 += __shfl_xor_sync(0xffffffffu, s0, 2);
        s1 += __shfl_xor_sync(0xffffffffu, s1, 1);
        s1 += __shfl_xor_sync(0xffffffffu, s1, 2);
        l0 = l0 * c0 + s0;
        l1 = l1 * c1 + s1;
        #pragma unroll
        for (int j = 0; j < 4; ++j) {
            oacc[j][0] *= c0; oacc[j][1] *= c0;
            oacc[j][2] *= c1; oacc[j][3] *= c1;
        }

        // ---- pack P into A fragments ----
        uint32_t a[4][4];
        #pragma unroll
        for (int kc = 0; kc < 4; ++kc) {
            a[kc][0] = pack_bf16(sc4[2 * kc][0],     sc4[2 * kc][1]);
            a[kc][1] = pack_bf16(sc4[2 * kc][2],     sc4[2 * kc][3]);
            a[kc][2] = pack_bf16(sc4[2 * kc + 1][0], sc4[2 * kc + 1][1]);
            a[kc][3] = pack_bf16(sc4[2 * kc + 1][2], sc4[2 * kc + 1][3]);
        }

        // ---- P @ V ----
        #pragma unroll
        for (int kc = 0; kc < 4; ++kc) {
            uint32_t vbf[2][4];
            #pragma unroll
            for (int half = 0; half < 2; ++half) {
                int grp = lane >> 3;
                int row = kc * 16 + ((grp & 1) << 3) + (lane & 7);
                int colb = half * 32 + ((grp >> 1) << 4);
                ldsm_x4_t(vbf[half], vsb + row * (AT_STRIDE * 2) + colb);
            }
            #pragma unroll
            for (int dj = 0; dj < 4; ++dj)
                mma_bf16(oacc[dj], a[kc], vbf[dj >> 1][(dj & 1) * 2], vbf[dj >> 1][(dj & 1) * 2 + 1]);
        }
        __syncthreads();
    }

    // ---- epilogue: normalize -> fp16 [token, 256] ----
    float inv0 = 1.0f / l0, inv1 = 1.0f / l1;
    int b = bh >> 3, h = bh & 7;
    int r0 = q0 + wid * 16 + (lane >> 2);
    __half* ob0 = att + (size_t)(b * SEQ + r0) * EMB;
    __half* ob1 = att + (size_t)(b * SEQ + r0 + 8) * EMB;
    #pragma unroll
    for (int dj = 0; dj < 4; ++dj) {
        int col = h * HDIM + dj * 8 + ((lane & 3) << 1);
        *(uint32_t*)(ob0 + col) = pack_f16(oacc[dj][0] * inv0, oacc[dj][1] * inv0);
        *(uint32_t*)(ob1 + col) = pack_f16(oacc[dj][2] * inv1, oacc[dj][3] * inv1);
    }
}

// ---------------- launcher ----------------
extern "C" void kernel_launch(void* const* d_in, const int* in_sizes, int n_in,
                              void* d_out, int out_size) {
    const float* src   = (const float*)d_in[0];
    const float* w_in  = (const float*)d_in[1];
    const float* w_out = (const float*)d_in[2];
    const float* w1    = (const float*)d_in[3];
    const float* b1    = (const float*)d_in[4];
    const float* w2    = (const float*)d_in[5];
    const float* b2    = (const float*)d_in[6];
    const float* g1    = (const float*)d_in[7];
    const float* be1   = (const float*)d_in[8];
    const float* g2    = (const float*)d_in[9];
    const float* be2   = (const float*)d_in[10];
    float* out = (float*)d_out;

    float *src2;
    __half *xs, *att, *ys, *hh, *wsin, *wsout, *w1s, *w2s;
    __nv_bfloat16 *qb, *kb, *vb;
    cudaGetSymbolAddress((void**)&src2,  g_src2);
    cudaGetSymbolAddress((void**)&xs,    g_xs);
    cudaGetSymbolAddress((void**)&att,   g_att);
    cudaGetSymbolAddress((void**)&ys,    g_ys);
    cudaGetSymbolAddress((void**)&hh,    g_hh);
    cudaGetSymbolAddress((void**)&qb,    g_q);
    cudaGetSymbolAddress((void**)&kb,    g_k);
    cudaGetSymbolAddress((void**)&vb,    g_v);
    cudaGetSymbolAddress((void**)&wsin,  g_wsin);
    cudaGetSymbolAddress((void**)&wsout, g_wsout);
    cudaGetSymbolAddress((void**)&w1s,   g_w1s);
    cudaGetSymbolAddress((void**)&w2s,   g_w2s);

    const int SMEM = 2 * GSTAGE;   // 96KB
    cudaFuncSetAttribute(gemm_f16_kernel<0>, cudaFuncAttributeMaxDynamicSharedMemorySize, SMEM);
    cudaFuncSetAttribute(gemm_f16_kernel<1>, cudaFuncAttributeMaxDynamicSharedMemorySize, SMEM);
    cudaFuncSetAttribute(gemm_f16_kernel<2>, cudaFuncAttributeMaxDynamicSharedMemorySize, SMEM);
    cudaFuncSetAttribute(gemm_f16_kernel<3>, cudaFuncAttributeMaxDynamicSharedMemorySize, SMEM);

    // weight splits (one kernel)
    split_w_all<<<3072, 256>>>(w_in, w_out, w1, w2, wsin, wsout, w1s, w2s);

    // 1) xs = fp16(LN1(src))
    ln_f16_kernel<<<NTOK / 8, 256>>>(src, g1, be1, xs);
    // 2) q,k,v = xs @ w_in^T  (bf16 per-head, q pre-scaled)
    gemm_f16_kernel<0><<<dim3(768 / 128, NTOK / 128), 256, SMEM>>>(
        xs, wsin, nullptr, nullptr, nullptr, nullptr, qb, kb, vb, EMB, 768);
    // 3) att = softmax(qk^T)v  (fp16)
    attn_mma_kernel<<<dim3(SEQ / 128, BATCH * HEADS), 256>>>(qb, kb, vb, att);
    // 4) src2 = src + att @ w_out^T
    gemm_f16_kernel<1><<<dim3(256 / 128, NTOK / 128), 256, SMEM>>>(
        att, wsout, nullptr, src, src2, nullptr, nullptr, nullptr, nullptr, EMB, 256);
    // 5) ys = fp16(LN2(src2))
    ln_f16_kernel<<<NTOK / 8, 256>>>(src2, g2, be2, ys);
    // 6) hh = fp16(relu(ys @ w1^T + b1))
    gemm_f16_kernel<2><<<dim3(1024 / 128, NTOK / 128), 256, SMEM>>>(
        ys, w1s, b1, nullptr, nullptr, hh, nullptr, nullptr, nullptr, EMB, 1024);
    // 7) out = src2 + hh @ w2^T + b2
    gemm_f16_kernel<3><<<dim3(256 / 128, NTOK / 128), 256, SMEM>>>(
        hh, w2s, b2, src2, out, nullptr, nullptr, nullptr, nullptr, FFN, 256);
}